// round 1
// baseline (speedup 1.0000x reference)
#include <cuda_runtime.h>
#include <math.h>

// ---------------- problem constants ----------------
#define BATCHN  16
#define LSEQ    2048
#define INDIM   64
#define HID     256
#define STATE   256
#define MLPD    1024
#define OUTD    128
#define NL      4
#define BL      (BATCHN * LSEQ)      // 32768 rows
#define CL      128                  // scan chunk length
#define NC      (LSEQ / CL)          // 16 chunks

// ---------------- device scratch (static, no allocations) ----------------
__device__ float g_h  [BL * HID];        // layer activations
__device__ float g_y  [BL * HID];        // LRU output y
__device__ float g_sre[BL * STATE];      // Bu / states (real)
__device__ float g_sim[BL * STATE];      // Bu / states (imag)
__device__ float g_z  [BL * MLPD];       // MLP hidden
__device__ float g_cre[BATCHN * NC * STATE];   // chunk carries
__device__ float g_cim[BATCHN * NC * STATE];
__device__ float g_ire[BATCHN * NC * STATE];   // chunk incoming prefixes
__device__ float g_iim[BATCHN * NC * STATE];
__device__ float g_lamre[NL * STATE];
__device__ float g_lamim[NL * STATE];
__device__ float g_eg   [NL * STATE];          // exp(gamma_log)
__device__ float g_negCim[NL * HID * STATE];   // -C_im

// ---------------- small prep kernels ----------------
__global__ void prep_kernel(const float* __restrict__ nu,
                            const float* __restrict__ th,
                            const float* __restrict__ gl) {
    const int l = blockIdx.x, s = threadIdx.x;
    const int idx = l * STATE + s;
    const float enu = expf(nu[idx]);
    const float eth = expf(th[idx]);
    const float mag = expf(-enu);
    g_lamre[idx] = mag * cosf(eth);
    g_lamim[idx] = mag * sinf(eth);
    g_eg[idx]    = expf(gl[idx]);
}

__global__ void neg_kernel(const float* __restrict__ Cim) {
    const int i = blockIdx.x * 256 + threadIdx.x;
    g_negCim[i] = -Cim[i];
}

// ---------------- chunked complex diagonal scan ----------------
// states[t] = lam * states[t-1] + Bu[t], lam constant per (layer, state)
__global__ void scan_pass1(int l) {   // local scans + chunk-final carries
    const int s = threadIdx.x, c = blockIdx.x, b = blockIdx.y;
    const float lr = g_lamre[l * STATE + s];
    const float li = g_lamim[l * STATE + s];
    size_t idx = ((size_t)(b * LSEQ + c * CL)) * STATE + s;
    float ar = 0.f, ai = 0.f;
    for (int t = 0; t < CL; ++t, idx += STATE) {
        const float br = g_sre[idx], bi = g_sim[idx];
        const float nr = fmaf(lr, ar, fmaf(-li, ai, br));
        const float ni = fmaf(lr, ai, fmaf( li, ar, bi));
        ar = nr; ai = ni;
        g_sre[idx] = ar; g_sim[idx] = ai;
    }
    const int ci = (b * NC + c) * STATE + s;
    g_cre[ci] = ar; g_cim[ci] = ai;
}

__global__ void scan_pass2(int l, const float* __restrict__ nu,
                           const float* __restrict__ th) {  // carry combine
    const int s = threadIdx.x, b = blockIdx.x;
    const float enu = expf(nu[l * STATE + s]);
    const float eth = expf(th[l * STATE + s]);
    // lam^CL computed in closed form: exp(-CL*enu) * cis(CL*eth)
    const float r   = expf(-(float)CL * enu);
    const float ang = (float)CL * eth;
    const float Ar = r * cosf(ang), Ai = r * sinf(ang);
    float pr = 0.f, pi = 0.f;
    for (int c = 0; c < NC; ++c) {
        const int ci = (b * NC + c) * STATE + s;
        g_ire[ci] = pr; g_iim[ci] = pi;
        const float cr = g_cre[ci], cii = g_cim[ci];
        const float nr = fmaf(Ar, pr, fmaf(-Ai, pi, cr));
        const float ni = fmaf(Ar, pi, fmaf( Ai, pr, cii));
        pr = nr; pi = ni;
    }
}

__global__ void scan_pass3(int l) {   // add lam^(t+1) * incoming prefix
    const int s = threadIdx.x, c = blockIdx.x, b = blockIdx.y;
    if (c == 0) return;
    const int ci = (b * NC + c) * STATE + s;
    const float fr = g_ire[ci], fi = g_iim[ci];
    if (fr == 0.f && fi == 0.f) return;
    const float lr = g_lamre[l * STATE + s];
    const float li = g_lamim[l * STATE + s];
    float pr = lr, pi = li;
    size_t idx = ((size_t)(b * LSEQ + c * CL)) * STATE + s;
    for (int t = 0; t < CL; ++t, idx += STATE) {
        g_sre[idx] = fmaf(pr, fr, fmaf(-pi, fi, g_sre[idx]));
        g_sim[idx] = fmaf(pr, fi, fmaf( pi, fr, g_sim[idx]));
        const float nr = pr * lr - pi * li;
        const float ni = fmaf(pr, li, pi * lr);
        pr = nr; pi = ni;
    }
}

// ---------------- tiled fp32 SGEMM:  C = A(MxK) @ W(NxK)^T  + epilogue -------
// EPI: 0 = +bias ; 1 = gelu(x+bias) ; 2 = +bias + res ; 3 = *scale[col] ;
//      4 = + scale[col] * res   (y = states@C^T + D*h)
// DUAL: accumulate a second (A2, W2) product with the same K.
template <int EPI, bool DUAL>
__global__ void __launch_bounds__(256)
sgemm_k(const float* __restrict__ A,  const float* __restrict__ W,
        const float* __restrict__ A2, const float* __restrict__ W2,
        float* __restrict__ Cout, int M, int N, int K,
        const float* __restrict__ bias, const float* __restrict__ scale,
        const float* __restrict__ res)
{
    __shared__ __align__(16) float As[2][8][128];
    __shared__ __align__(16) float Bs[2][8][128];

    const int tid  = threadIdx.x;
    const int tx   = tid & 15;
    const int ty   = tid >> 4;
    const int row0 = blockIdx.y * 128;
    const int col0 = blockIdx.x * 128;
    const int lrow = tid >> 1;          // 0..127
    const int lk   = (tid & 1) << 2;    // 0 or 4

    float acc[8][8];
#pragma unroll
    for (int i = 0; i < 8; ++i)
#pragma unroll
        for (int j = 0; j < 8; ++j) acc[i][j] = 0.f;

    const int npass = DUAL ? 2 : 1;
    for (int pass = 0; pass < npass; ++pass) {
        const float* Ap = (DUAL && pass) ? A2 : A;
        const float* Wp = (DUAL && pass) ? W2 : W;
        const float* aPtr = Ap + (size_t)(row0 + lrow) * K + lk;
        const float* wPtr = Wp + (size_t)(col0 + lrow) * K + lk;

        __syncthreads();   // protect smem reuse across passes (no-op cost on pass 0)
        float4 av = *(const float4*)aPtr;
        float4 wv = *(const float4*)wPtr;
        int buf = 0;
        As[0][lk+0][lrow]=av.x; As[0][lk+1][lrow]=av.y; As[0][lk+2][lrow]=av.z; As[0][lk+3][lrow]=av.w;
        Bs[0][lk+0][lrow]=wv.x; Bs[0][lk+1][lrow]=wv.y; Bs[0][lk+2][lrow]=wv.z; Bs[0][lk+3][lrow]=wv.w;
        __syncthreads();

        const int KT = K >> 3;
        for (int kt = 0; kt < KT; ++kt) {
            if (kt + 1 < KT) {
                av = *(const float4*)(aPtr + (size_t)(kt + 1) * 8);
                wv = *(const float4*)(wPtr + (size_t)(kt + 1) * 8);
            }
#pragma unroll
            for (int kk = 0; kk < 8; ++kk) {
                const float4 a0 = *(const float4*)&As[buf][kk][ty * 8];
                const float4 a1 = *(const float4*)&As[buf][kk][ty * 8 + 4];
                const float4 b0 = *(const float4*)&Bs[buf][kk][tx * 8];
                const float4 b1 = *(const float4*)&Bs[buf][kk][tx * 8 + 4];
                const float af[8] = {a0.x, a0.y, a0.z, a0.w, a1.x, a1.y, a1.z, a1.w};
                const float bf[8] = {b0.x, b0.y, b0.z, b0.w, b1.x, b1.y, b1.z, b1.w};
#pragma unroll
                for (int i = 0; i < 8; ++i)
#pragma unroll
                    for (int j = 0; j < 8; ++j)
                        acc[i][j] = fmaf(af[i], bf[j], acc[i][j]);
            }
            if (kt + 1 < KT) {
                buf ^= 1;
                As[buf][lk+0][lrow]=av.x; As[buf][lk+1][lrow]=av.y; As[buf][lk+2][lrow]=av.z; As[buf][lk+3][lrow]=av.w;
                Bs[buf][lk+0][lrow]=wv.x; Bs[buf][lk+1][lrow]=wv.y; Bs[buf][lk+2][lrow]=wv.z; Bs[buf][lk+3][lrow]=wv.w;
                __syncthreads();
            }
        }
    }

    // epilogue
#pragma unroll
    for (int i = 0; i < 8; ++i) {
        const size_t r = (size_t)(row0 + ty * 8 + i);
#pragma unroll
        for (int j = 0; j < 8; ++j) {
            const size_t c = (size_t)(col0 + tx * 8 + j);
            float v = acc[i][j];
            if (EPI == 0) v += bias[c];
            if (EPI == 1) { const float t = v + bias[c];
                            v = 0.5f * t * (1.0f + erff(t * 0.7071067811865476f)); }
            if (EPI == 2) v += bias[c] + res[r * (size_t)N + c];
            if (EPI == 3) v *= scale[c];
            if (EPI == 4) v = fmaf(scale[c], res[r * (size_t)N + c], v);
            Cout[r * (size_t)N + c] = v;
        }
    }
}

// ---------------- launch ----------------
extern "C" void kernel_launch(void* const* d_in, const int* in_sizes, int n_in,
                              void* d_out, int out_size)
{
    (void)in_sizes; (void)n_in; (void)out_size;
    const float* x    = (const float*)d_in[0];
    const float* embW = (const float*)d_in[1];
    const float* embB = (const float*)d_in[2];
    const float* nu   = (const float*)d_in[3];
    const float* th   = (const float*)d_in[4];
    const float* gl   = (const float*)d_in[5];
    const float* Bre  = (const float*)d_in[6];
    const float* Bim  = (const float*)d_in[7];
    const float* Cre  = (const float*)d_in[8];
    const float* Cim  = (const float*)d_in[9];
    const float* Dm   = (const float*)d_in[10];
    const float* Wh   = (const float*)d_in[11];
    const float* bh   = (const float*)d_in[12];
    const float* Wo   = (const float*)d_in[13];
    const float* bo   = (const float*)d_in[14];
    const float* outW = (const float*)d_in[15];
    const float* outB = (const float*)d_in[16];
    float* out = (float*)d_out;

    float *h, *y, *sre, *sim, *z, *eg, *negc;
    cudaGetSymbolAddress((void**)&h,    g_h);
    cudaGetSymbolAddress((void**)&y,    g_y);
    cudaGetSymbolAddress((void**)&sre,  g_sre);
    cudaGetSymbolAddress((void**)&sim,  g_sim);
    cudaGetSymbolAddress((void**)&z,    g_z);
    cudaGetSymbolAddress((void**)&eg,   g_eg);
    cudaGetSymbolAddress((void**)&negc, g_negCim);

    prep_kernel<<<NL, STATE>>>(nu, th, gl);
    neg_kernel<<<(NL * HID * STATE) / 256, 256>>>(Cim);

    // embedding: h = x @ embW^T + embB          (BL x 256, K=64)
    sgemm_k<0, false><<<dim3(HID / 128, BL / 128), 256>>>(
        x, embW, nullptr, nullptr, h, BL, HID, INDIM, embB, nullptr, nullptr);

    for (int l = 0; l < NL; ++l) {
        // Bu = (h @ B^T) * exp(gamma)[col]      (BL x 256, K=256) x2
        sgemm_k<3, false><<<dim3(STATE / 128, BL / 128), 256>>>(
            h, Bre + (size_t)l * STATE * HID, nullptr, nullptr, sre,
            BL, STATE, HID, nullptr, eg + l * STATE, nullptr);
        sgemm_k<3, false><<<dim3(STATE / 128, BL / 128), 256>>>(
            h, Bim + (size_t)l * STATE * HID, nullptr, nullptr, sim,
            BL, STATE, HID, nullptr, eg + l * STATE, nullptr);

        // diagonal complex scan (in place on sre/sim)
        scan_pass1<<<dim3(NC, BATCHN), STATE>>>(l);
        scan_pass2<<<BATCHN, STATE>>>(l, nu, th);
        scan_pass3<<<dim3(NC, BATCHN), STATE>>>(l);

        // y = Re(states @ C^T) + D * h = sre@Cre^T + sim@(-Cim)^T + D[col]*h
        sgemm_k<4, true><<<dim3(HID / 128, BL / 128), 256>>>(
            sre, Cre + (size_t)l * HID * STATE,
            sim, negc + (size_t)l * HID * STATE, y,
            BL, HID, STATE, nullptr, Dm + l * HID, h);

        // z = gelu(y @ Wh^T + bh)               (BL x 1024, K=256)
        sgemm_k<1, false><<<dim3(MLPD / 128, BL / 128), 256>>>(
            y, Wh + (size_t)l * MLPD * STATE, nullptr, nullptr, z,
            BL, MLPD, STATE, bh + l * MLPD, nullptr, nullptr);

        // h = z @ Wo^T + bo + y                 (BL x 256, K=1024)
        sgemm_k<2, false><<<dim3(HID / 128, BL / 128), 256>>>(
            z, Wo + (size_t)l * HID * MLPD, nullptr, nullptr, h,
            BL, HID, MLPD, bo + l * HID, nullptr, y);
    }

    // out = h @ outW^T + outB                   (BL x 128, K=256)
    sgemm_k<0, false><<<dim3(OUTD / 128, BL / 128), 256>>>(
        h, outW, nullptr, nullptr, out, BL, OUTD, HID, outB, nullptr, nullptr);
}

// round 2
// speedup vs baseline: 1.0308x; 1.0308x over previous
#include <cuda_runtime.h>
#include <math.h>

// ---------------- problem constants ----------------
#define BATCHN  16
#define LSEQ    2048
#define INDIM   64
#define HID     256
#define STATE   256
#define MLPD    1024
#define OUTD    128
#define NL      4
#define BL      (BATCHN * LSEQ)      // 32768 rows
#define CL      128                  // scan chunk length
#define NC      (LSEQ / CL)          // 16 chunks

typedef unsigned long long u64;

// ---------------- f32x2 packed-FMA helpers (Blackwell, PTX-only) ----------
__device__ __forceinline__ u64 pack2(float lo, float hi) {
    u64 r; asm("mov.b64 %0, {%1,%2};" : "=l"(r) : "f"(lo), "f"(hi)); return r;
}
__device__ __forceinline__ void fma2(u64& c, u64 a, u64 b) {
    asm("fma.rn.f32x2 %0, %1, %2, %0;" : "+l"(c) : "l"(a), "l"(b));
}
__device__ __forceinline__ float2 unpack2(u64 v) {
    float2 f; asm("mov.b64 {%0,%1}, %2;" : "=f"(f.x), "=f"(f.y) : "l"(v)); return f;
}

// ---------------- device scratch (static, no allocations) ----------------
__device__ float g_h  [BL * HID];        // layer activations
__device__ float g_y  [BL * HID];        // LRU output y
__device__ float g_sre[BL * STATE];      // Bu / states (real)
__device__ float g_sim[BL * STATE];      // Bu / states (imag)
__device__ float g_z  [BL * MLPD];       // MLP hidden
__device__ float g_cre[BATCHN * NC * STATE];   // chunk carries
__device__ float g_cim[BATCHN * NC * STATE];
__device__ float g_ire[BATCHN * NC * STATE];   // chunk incoming prefixes
__device__ float g_iim[BATCHN * NC * STATE];
__device__ float g_lamre[NL * STATE];
__device__ float g_lamim[NL * STATE];
__device__ float g_eg   [NL * STATE];          // exp(gamma_log)
__device__ float g_negCim[NL * HID * STATE];   // -C_im

// ---------------- small prep kernels ----------------
__global__ void prep_kernel(const float* __restrict__ nu,
                            const float* __restrict__ th,
                            const float* __restrict__ gl) {
    const int l = blockIdx.x, s = threadIdx.x;
    const int idx = l * STATE + s;
    const float enu = expf(nu[idx]);
    const float eth = expf(th[idx]);
    const float mag = expf(-enu);
    g_lamre[idx] = mag * cosf(eth);
    g_lamim[idx] = mag * sinf(eth);
    g_eg[idx]    = expf(gl[idx]);
}

__global__ void neg_kernel(const float* __restrict__ Cim) {
    const int i = blockIdx.x * 256 + threadIdx.x;
    g_negCim[i] = -Cim[i];
}

// ---------------- chunked complex diagonal scan ----------------
__global__ void scan_pass1(int l) {   // local scans + chunk-final carries
    const int s = threadIdx.x, c = blockIdx.x, b = blockIdx.y;
    const float lr = g_lamre[l * STATE + s];
    const float li = g_lamim[l * STATE + s];
    size_t idx = ((size_t)(b * LSEQ + c * CL)) * STATE + s;
    float ar = 0.f, ai = 0.f;
    for (int t = 0; t < CL; ++t, idx += STATE) {
        const float br = g_sre[idx], bi = g_sim[idx];
        const float nr = fmaf(lr, ar, fmaf(-li, ai, br));
        const float ni = fmaf(lr, ai, fmaf( li, ar, bi));
        ar = nr; ai = ni;
        g_sre[idx] = ar; g_sim[idx] = ai;
    }
    const int ci = (b * NC + c) * STATE + s;
    g_cre[ci] = ar; g_cim[ci] = ai;
}

__global__ void scan_pass2(int l, const float* __restrict__ nu,
                           const float* __restrict__ th) {  // carry combine
    const int s = threadIdx.x, b = blockIdx.x;
    const float enu = expf(nu[l * STATE + s]);
    const float eth = expf(th[l * STATE + s]);
    const float r   = expf(-(float)CL * enu);
    const float ang = (float)CL * eth;
    const float Ar = r * cosf(ang), Ai = r * sinf(ang);
    float pr = 0.f, pi = 0.f;
    for (int c = 0; c < NC; ++c) {
        const int ci = (b * NC + c) * STATE + s;
        g_ire[ci] = pr; g_iim[ci] = pi;
        const float cr = g_cre[ci], cii = g_cim[ci];
        const float nr = fmaf(Ar, pr, fmaf(-Ai, pi, cr));
        const float ni = fmaf(Ar, pi, fmaf( Ai, pr, cii));
        pr = nr; pi = ni;
    }
}

__global__ void scan_pass3(int l) {   // add lam^(t+1) * incoming prefix
    const int s = threadIdx.x, c = blockIdx.x, b = blockIdx.y;
    if (c == 0) return;
    const int ci = (b * NC + c) * STATE + s;
    const float fr = g_ire[ci], fi = g_iim[ci];
    if (fr == 0.f && fi == 0.f) return;
    const float lr = g_lamre[l * STATE + s];
    const float li = g_lamim[l * STATE + s];
    float pr = lr, pi = li;
    size_t idx = ((size_t)(b * LSEQ + c * CL)) * STATE + s;
    for (int t = 0; t < CL; ++t, idx += STATE) {
        g_sre[idx] = fmaf(pr, fr, fmaf(-pi, fi, g_sre[idx]));
        g_sim[idx] = fmaf(pr, fi, fmaf( pi, fr, g_sim[idx]));
        const float nr = pr * lr - pi * li;
        const float ni = fmaf(pr, li, pi * lr);
        pr = nr; pi = ni;
    }
}

// ---------------- tiled fp32 SGEMM with f32x2 packed FMA --------------------
//  C = A(MxK) @ W(NxK)^T  + epilogue
// EPI: 0 = +bias ; 1 = gelu(x+bias) ; 2 = +bias + res ; 3 = *scale[col] ;
//      4 = + scale[col] * res
// DUAL: accumulate a second (A2, W2) product with the same K.
template <int EPI, bool DUAL>
__global__ void __launch_bounds__(256)
sgemm_k(const float* __restrict__ A,  const float* __restrict__ W,
        const float* __restrict__ A2, const float* __restrict__ W2,
        float* __restrict__ Cout, int M, int N, int K,
        const float* __restrict__ bias, const float* __restrict__ scale,
        const float* __restrict__ res)
{
    __shared__ __align__(16) float As[2][8][128];
    __shared__ __align__(16) float Bs[2][8][128];

    const int tid  = threadIdx.x;
    const int tx   = tid & 15;
    const int ty   = tid >> 4;
    const int row0 = blockIdx.y * 128;
    const int col0 = blockIdx.x * 128;
    const int lrow = tid >> 1;          // 0..127
    const int lk   = (tid & 1) << 2;    // 0 or 4

    // 8 rows x 8 cols per thread, cols packed as 4 f32x2 pairs
    u64 acc[8][4];
#pragma unroll
    for (int i = 0; i < 8; ++i)
#pragma unroll
        for (int j = 0; j < 4; ++j) acc[i][j] = 0ull;

    const int npass = DUAL ? 2 : 1;
    for (int pass = 0; pass < npass; ++pass) {
        const float* Ap = (DUAL && pass) ? A2 : A;
        const float* Wp = (DUAL && pass) ? W2 : W;
        const float* aPtr = Ap + (size_t)(row0 + lrow) * K + lk;
        const float* wPtr = Wp + (size_t)(col0 + lrow) * K + lk;

        __syncthreads();   // protect smem reuse across passes
        float4 av = *(const float4*)aPtr;
        float4 wv = *(const float4*)wPtr;
        int buf = 0;
        As[0][lk+0][lrow]=av.x; As[0][lk+1][lrow]=av.y; As[0][lk+2][lrow]=av.z; As[0][lk+3][lrow]=av.w;
        Bs[0][lk+0][lrow]=wv.x; Bs[0][lk+1][lrow]=wv.y; Bs[0][lk+2][lrow]=wv.z; Bs[0][lk+3][lrow]=wv.w;
        __syncthreads();

        const int KT = K >> 3;
        for (int kt = 0; kt < KT; ++kt) {
            if (kt + 1 < KT) {
                av = *(const float4*)(aPtr + (size_t)(kt + 1) * 8);
                wv = *(const float4*)(wPtr + (size_t)(kt + 1) * 8);
            }
#pragma unroll
            for (int kk = 0; kk < 8; ++kk) {
                const float4 a0 = *(const float4*)&As[buf][kk][ty * 8];
                const float4 a1 = *(const float4*)&As[buf][kk][ty * 8 + 4];
                // B pairs arrive packed directly from the 128-bit shared load
                const ulonglong2 bb0 = *(const ulonglong2*)&Bs[buf][kk][tx * 8];
                const ulonglong2 bb1 = *(const ulonglong2*)&Bs[buf][kk][tx * 8 + 4];
                const u64 b2[4] = {bb0.x, bb0.y, bb1.x, bb1.y};
                const float af[8] = {a0.x, a0.y, a0.z, a0.w, a1.x, a1.y, a1.z, a1.w};
#pragma unroll
                for (int i = 0; i < 8; ++i) {
                    const u64 ad = pack2(af[i], af[i]);
#pragma unroll
                    for (int j = 0; j < 4; ++j)
                        fma2(acc[i][j], ad, b2[j]);
                }
            }
            if (kt + 1 < KT) {
                buf ^= 1;
                As[buf][lk+0][lrow]=av.x; As[buf][lk+1][lrow]=av.y; As[buf][lk+2][lrow]=av.z; As[buf][lk+3][lrow]=av.w;
                Bs[buf][lk+0][lrow]=wv.x; Bs[buf][lk+1][lrow]=wv.y; Bs[buf][lk+2][lrow]=wv.z; Bs[buf][lk+3][lrow]=wv.w;
                __syncthreads();
            }
        }
    }

    // epilogue
#pragma unroll
    for (int i = 0; i < 8; ++i) {
        const size_t r = (size_t)(row0 + ty * 8 + i);
#pragma unroll
        for (int j = 0; j < 4; ++j) {
            const float2 p = unpack2(acc[i][j]);
            float vv[2] = {p.x, p.y};
#pragma unroll
            for (int e = 0; e < 2; ++e) {
                const size_t c = (size_t)(col0 + tx * 8 + 2 * j + e);
                float v = vv[e];
                if (EPI == 0) v += bias[c];
                if (EPI == 1) { const float t = v + bias[c];
                                v = 0.5f * t * (1.0f + erff(t * 0.7071067811865476f)); }
                if (EPI == 2) v += bias[c] + res[r * (size_t)N + c];
                if (EPI == 3) v *= scale[c];
                if (EPI == 4) v = fmaf(scale[c], res[r * (size_t)N + c], v);
                Cout[r * (size_t)N + c] = v;
            }
        }
    }
}

// ---------------- launch ----------------
extern "C" void kernel_launch(void* const* d_in, const int* in_sizes, int n_in,
                              void* d_out, int out_size)
{
    (void)in_sizes; (void)n_in; (void)out_size;
    const float* x    = (const float*)d_in[0];
    const float* embW = (const float*)d_in[1];
    const float* embB = (const float*)d_in[2];
    const float* nu   = (const float*)d_in[3];
    const float* th   = (const float*)d_in[4];
    const float* gl   = (const float*)d_in[5];
    const float* Bre  = (const float*)d_in[6];
    const float* Bim  = (const float*)d_in[7];
    const float* Cre  = (const float*)d_in[8];
    const float* Cim  = (const float*)d_in[9];
    const float* Dm   = (const float*)d_in[10];
    const float* Wh   = (const float*)d_in[11];
    const float* bh   = (const float*)d_in[12];
    const float* Wo   = (const float*)d_in[13];
    const float* bo   = (const float*)d_in[14];
    const float* outW = (const float*)d_in[15];
    const float* outB = (const float*)d_in[16];
    float* out = (float*)d_out;

    float *h, *y, *sre, *sim, *z, *eg, *negc;
    cudaGetSymbolAddress((void**)&h,    g_h);
    cudaGetSymbolAddress((void**)&y,    g_y);
    cudaGetSymbolAddress((void**)&sre,  g_sre);
    cudaGetSymbolAddress((void**)&sim,  g_sim);
    cudaGetSymbolAddress((void**)&z,    g_z);
    cudaGetSymbolAddress((void**)&eg,   g_eg);
    cudaGetSymbolAddress((void**)&negc, g_negCim);

    prep_kernel<<<NL, STATE>>>(nu, th, gl);
    neg_kernel<<<(NL * HID * STATE) / 256, 256>>>(Cim);

    // embedding: h = x @ embW^T + embB          (BL x 256, K=64)
    sgemm_k<0, false><<<dim3(HID / 128, BL / 128), 256>>>(
        x, embW, nullptr, nullptr, h, BL, HID, INDIM, embB, nullptr, nullptr);

    for (int l = 0; l < NL; ++l) {
        // Bu = (h @ B^T) * exp(gamma)[col]      (BL x 256, K=256) x2
        sgemm_k<3, false><<<dim3(STATE / 128, BL / 128), 256>>>(
            h, Bre + (size_t)l * STATE * HID, nullptr, nullptr, sre,
            BL, STATE, HID, nullptr, eg + l * STATE, nullptr);
        sgemm_k<3, false><<<dim3(STATE / 128, BL / 128), 256>>>(
            h, Bim + (size_t)l * STATE * HID, nullptr, nullptr, sim,
            BL, STATE, HID, nullptr, eg + l * STATE, nullptr);

        // diagonal complex scan (in place on sre/sim)
        scan_pass1<<<dim3(NC, BATCHN), STATE>>>(l);
        scan_pass2<<<BATCHN, STATE>>>(l, nu, th);
        scan_pass3<<<dim3(NC, BATCHN), STATE>>>(l);

        // y = Re(states @ C^T) + D * h
        sgemm_k<4, true><<<dim3(HID / 128, BL / 128), 256>>>(
            sre, Cre + (size_t)l * HID * STATE,
            sim, negc + (size_t)l * HID * STATE, y,
            BL, HID, STATE, nullptr, Dm + l * HID, h);

        // z = gelu(y @ Wh^T + bh)               (BL x 1024, K=256)
        sgemm_k<1, false><<<dim3(MLPD / 128, BL / 128), 256>>>(
            y, Wh + (size_t)l * MLPD * STATE, nullptr, nullptr, z,
            BL, MLPD, STATE, bh + l * MLPD, nullptr, nullptr);

        // h = z @ Wo^T + bo + y                 (BL x 256, K=1024)
        sgemm_k<2, false><<<dim3(HID / 128, BL / 128), 256>>>(
            z, Wo + (size_t)l * HID * MLPD, nullptr, nullptr, h,
            BL, HID, MLPD, bo + l * HID, nullptr, y);
    }

    // out = h @ outW^T + outB                   (BL x 128, K=256)
    sgemm_k<0, false><<<dim3(OUTD / 128, BL / 128), 256>>>(
        h, outW, nullptr, nullptr, out, BL, OUTD, HID, outB, nullptr, nullptr);
}

// round 4
// speedup vs baseline: 2.4704x; 2.3966x over previous
#include <cuda_runtime.h>
#include <math.h>
#include <stdint.h>

// ---------------- problem constants ----------------
#define BATCHN  16
#define LSEQ    2048
#define INDIM   64
#define HID     256
#define STATE   256
#define MLPD    1024
#define OUTD    128
#define NL      4
#define BL      (BATCHN * LSEQ)      // 32768 rows
#define CL      128                  // scan chunk length
#define NC      (LSEQ / CL)          // 16 chunks

// smem tile layout (bytes): rows padded to 80B (40 bf16) — conflict-free ldmatrix
#define LDS_ROW   80
#define T_AH      0
#define T_AL      10240
#define T_BH      20480
#define T_BL      30720
#define STAGE_B   40960
#define SMEM_BYTES (2 * STAGE_B)

// ---------------- device scratch (static, no allocations) ----------------
__device__ float g_h  [BL * HID];
__device__ float g_y  [BL * HID];
__device__ float g_sre[BL * STATE];
__device__ float g_sim[BL * STATE];
__device__ float g_z  [BL * MLPD];
__device__ float g_cre[BATCHN * NC * STATE];
__device__ float g_cim[BATCHN * NC * STATE];
__device__ float g_ire[BATCHN * NC * STATE];
__device__ float g_iim[BATCHN * NC * STATE];
__device__ float g_lamre[NL * STATE];
__device__ float g_lamim[NL * STATE];
__device__ float g_eg   [NL * STATE];
__device__ float g_negCim[NL * HID * STATE];

// ---------------- PTX helpers ----------------
__device__ __forceinline__ uint32_t smem_u32(const void* p) {
    uint32_t a;
    asm("{ .reg .u64 t; cvta.to.shared.u64 t, %1; cvt.u32.u64 %0, t; }"
        : "=r"(a) : "l"(p));
    return a;
}
// pack two fp32 -> bf16x2 (x in low half, y in high half)
__device__ __forceinline__ uint32_t cvt2(float x, float y) {
    uint32_t r;
    asm("cvt.rn.bf16x2.f32 %0, %1, %2;" : "=r"(r) : "f"(y), "f"(x));
    return r;
}
__device__ __forceinline__ float lo_of(uint32_t h) { return __uint_as_float(h << 16); }
__device__ __forceinline__ float hi_of(uint32_t h) { return __uint_as_float(h & 0xFFFF0000u); }
__device__ __forceinline__ void sts64(uint32_t a, uint32_t x, uint32_t y) {
    asm volatile("st.shared.v2.b32 [%0], {%1, %2};" :: "r"(a), "r"(x), "r"(y) : "memory");
}
#define LDSM4(r0, r1, r2, r3, addr) \
    asm volatile("ldmatrix.sync.aligned.m8n8.x4.shared.b16 {%0,%1,%2,%3}, [%4];" \
                 : "=r"(r0), "=r"(r1), "=r"(r2), "=r"(r3) : "r"(addr))
#define MMA_BF16(d, a, b) \
    asm volatile("mma.sync.aligned.m16n8k16.row.col.f32.bf16.bf16.f32 " \
                 "{%0,%1,%2,%3},{%4,%5,%6,%7},{%8,%9},{%0,%1,%2,%3};" \
                 : "+f"((d)[0]), "+f"((d)[1]), "+f"((d)[2]), "+f"((d)[3]) \
                 : "r"((a)[0]), "r"((a)[1]), "r"((a)[2]), "r"((a)[3]), \
                   "r"((b)[0]), "r"((b)[1]))

// ---------------- small prep kernels ----------------
__global__ void prep_kernel(const float* __restrict__ nu,
                            const float* __restrict__ th,
                            const float* __restrict__ gl) {
    const int l = blockIdx.x, s = threadIdx.x;
    const int idx = l * STATE + s;
    const float enu = expf(nu[idx]);
    const float eth = expf(th[idx]);
    const float mag = expf(-enu);
    g_lamre[idx] = mag * cosf(eth);
    g_lamim[idx] = mag * sinf(eth);
    g_eg[idx]    = expf(gl[idx]);
}

__global__ void neg_kernel(const float* __restrict__ Cim) {
    const int i = blockIdx.x * 256 + threadIdx.x;
    g_negCim[i] = -Cim[i];
}

// ---------------- chunked complex diagonal scan ----------------
__global__ void scan_pass1(int l) {
    const int s = threadIdx.x, c = blockIdx.x, b = blockIdx.y;
    const float lr = g_lamre[l * STATE + s];
    const float li = g_lamim[l * STATE + s];
    size_t idx = ((size_t)(b * LSEQ + c * CL)) * STATE + s;
    float ar = 0.f, ai = 0.f;
    for (int t = 0; t < CL; ++t, idx += STATE) {
        const float br = g_sre[idx], bi = g_sim[idx];
        const float nr = fmaf(lr, ar, fmaf(-li, ai, br));
        const float ni = fmaf(lr, ai, fmaf( li, ar, bi));
        ar = nr; ai = ni;
        g_sre[idx] = ar; g_sim[idx] = ai;
    }
    const int ci = (b * NC + c) * STATE + s;
    g_cre[ci] = ar; g_cim[ci] = ai;
}

__global__ void scan_pass2(int l, const float* __restrict__ nu,
                           const float* __restrict__ th) {
    const int s = threadIdx.x, b = blockIdx.x;
    const float enu = expf(nu[l * STATE + s]);
    const float eth = expf(th[l * STATE + s]);
    const float r   = expf(-(float)CL * enu);
    const float ang = (float)CL * eth;
    const float Ar = r * cosf(ang), Ai = r * sinf(ang);
    float pr = 0.f, pi = 0.f;
    for (int c = 0; c < NC; ++c) {
        const int ci = (b * NC + c) * STATE + s;
        g_ire[ci] = pr; g_iim[ci] = pi;
        const float cr = g_cre[ci], cii = g_cim[ci];
        const float nr = fmaf(Ar, pr, fmaf(-Ai, pi, cr));
        const float ni = fmaf(Ar, pi, fmaf( Ai, pr, cii));
        pr = nr; pi = ni;
    }
}

__global__ void scan_pass3(int l) {
    const int s = threadIdx.x, c = blockIdx.x, b = blockIdx.y;
    if (c == 0) return;
    const int ci = (b * NC + c) * STATE + s;
    const float fr = g_ire[ci], fi = g_iim[ci];
    if (fr == 0.f && fi == 0.f) return;
    const float lr = g_lamre[l * STATE + s];
    const float li = g_lamim[l * STATE + s];
    float pr = lr, pi = li;
    size_t idx = ((size_t)(b * LSEQ + c * CL)) * STATE + s;
    for (int t = 0; t < CL; ++t, idx += STATE) {
        g_sre[idx] = fmaf(pr, fr, fmaf(-pi, fi, g_sre[idx]));
        g_sim[idx] = fmaf(pr, fi, fmaf( pi, fr, g_sim[idx]));
        const float nr = pr * lr - pi * li;
        const float ni = fmaf(pr, li, pi * lr);
        pr = nr; pi = ni;
    }
}

// ---------------- stage store: fp32 float4 -> hi/lo bf16 smem ----------------
__device__ __forceinline__ void store_stage(uint32_t base, const float4* pA,
                                            const float4* pB, int tid)
{
#pragma unroll
    for (int i = 0; i < 4; ++i) {
        const int slot = i * 256 + tid;
        const int r = slot >> 3, c4 = slot & 7;
        const uint32_t off = (uint32_t)(r * LDS_ROW + c4 * 8);
        {
            const float4 f = pA[i];
            const uint32_t h0 = cvt2(f.x, f.y), h1 = cvt2(f.z, f.w);
            const uint32_t l0 = cvt2(f.x - lo_of(h0), f.y - hi_of(h0));
            const uint32_t l1 = cvt2(f.z - lo_of(h1), f.w - hi_of(h1));
            sts64(base + T_AH + off, h0, h1);
            sts64(base + T_AL + off, l0, l1);
        }
        {
            const float4 f = pB[i];
            const uint32_t h0 = cvt2(f.x, f.y), h1 = cvt2(f.z, f.w);
            const uint32_t l0 = cvt2(f.x - lo_of(h0), f.y - hi_of(h0));
            const uint32_t l1 = cvt2(f.z - lo_of(h1), f.w - hi_of(h1));
            sts64(base + T_BH + off, h0, h1);
            sts64(base + T_BL + off, l0, l1);
        }
    }
}

// ---------------- bf16x3 warp-MMA GEMM: C = A(MxK) @ W(NxK)^T + epilogue -----
// EPI: 0=+bias 1=gelu(x+bias) 2=+bias+res 3=*scale[col] 4=+scale[col]*res
// DUAL: accumulate a second (A2, W2) product with the same K.
template <int EPI, bool DUAL>
__global__ void __launch_bounds__(256, 1)
mma_gemm(const float* __restrict__ A,  const float* __restrict__ W,
         const float* __restrict__ A2, const float* __restrict__ W2,
         float* __restrict__ Cout, int N, int K,
         const float* __restrict__ bias, const float* __restrict__ scale,
         const float* __restrict__ res)
{
    extern __shared__ char smem[];
    const uint32_t sb = smem_u32(smem);
    const int tid  = threadIdx.x;
    const int lane = tid & 31, wid = tid >> 5;
    const int wm = wid & 3, wn = wid >> 2;          // warp grid 4(M) x 2(N)
    const int row0 = blockIdx.y * 128, col0 = blockIdx.x * 128;

    float acc[2][8][4];
#pragma unroll
    for (int mt = 0; mt < 2; ++mt)
#pragma unroll
        for (int nt = 0; nt < 8; ++nt)
#pragma unroll
            for (int e = 0; e < 4; ++e) acc[mt][nt][e] = 0.f;

    const int KC   = K >> 5;
    const int CTOT = DUAL ? 2 * KC : KC;

    // ldmatrix per-lane offsets (bytes within a hi/lo tile)
    const uint32_t aOff = (uint32_t)((wm * 32 + (lane & 15)) * LDS_ROW + ((lane >> 4) << 4));
    const uint32_t bOff = (uint32_t)((wn * 64 + (((lane >> 4) << 3) | (lane & 7))) * LDS_ROW
                                     + (((lane >> 3) & 1) << 4));

    // prologue: chunk 0
    float4 pA[4], pB[4];
#pragma unroll
    for (int i = 0; i < 4; ++i) {
        const int slot = i * 256 + tid, r = slot >> 3, c4 = slot & 7;
        pA[i] = *(const float4*)(A + (size_t)(row0 + r) * K + c4 * 4);
        pB[i] = *(const float4*)(W + (size_t)(col0 + r) * K + c4 * 4);
    }
    store_stage(sb, pA, pB, tid);
    __syncthreads();

    for (int c = 0; c < CTOT; ++c) {
        if (c + 1 < CTOT) {   // prefetch next chunk to registers
            const int pass = (DUAL && (c + 1) >= KC) ? 1 : 0;
            const int k0 = ((c + 1) - (pass ? KC : 0)) << 5;
            const float* Ap = pass ? A2 : A;
            const float* Wp = pass ? W2 : W;
#pragma unroll
            for (int i = 0; i < 4; ++i) {
                const int slot = i * 256 + tid, r = slot >> 3, c4 = slot & 7;
                pA[i] = *(const float4*)(Ap + (size_t)(row0 + r) * K + k0 + c4 * 4);
                pB[i] = *(const float4*)(Wp + (size_t)(col0 + r) * K + k0 + c4 * 4);
            }
        }
        const uint32_t st = sb + (uint32_t)(c & 1) * STAGE_B;
#pragma unroll
        for (int ks = 0; ks < 2; ++ks) {
            uint32_t ah[2][4], al[2][4], bh[8][2], bl[8][2];
            const uint32_t kb = (uint32_t)(ks * 32);
#pragma unroll
            for (int mt = 0; mt < 2; ++mt) {
                const uint32_t ad = st + aOff + (uint32_t)(mt * 16 * LDS_ROW) + kb;
                LDSM4(ah[mt][0], ah[mt][1], ah[mt][2], ah[mt][3], ad + T_AH);
                LDSM4(al[mt][0], al[mt][1], al[mt][2], al[mt][3], ad + T_AL);
            }
#pragma unroll
            for (int np = 0; np < 4; ++np) {
                const uint32_t bd = st + bOff + (uint32_t)(np * 16 * LDS_ROW) + kb;
                LDSM4(bh[np*2][0], bh[np*2][1], bh[np*2+1][0], bh[np*2+1][1], bd + T_BH);
                LDSM4(bl[np*2][0], bl[np*2][1], bl[np*2+1][0], bl[np*2+1][1], bd + T_BL);
            }
#pragma unroll
            for (int mt = 0; mt < 2; ++mt)
#pragma unroll
                for (int nt = 0; nt < 8; ++nt) {
                    MMA_BF16(acc[mt][nt], ah[mt], bh[nt]);
                    MMA_BF16(acc[mt][nt], al[mt], bh[nt]);
                    MMA_BF16(acc[mt][nt], ah[mt], bl[nt]);
                }
        }
        if (c + 1 < CTOT) {
            __syncthreads();
            store_stage(sb + (uint32_t)((c + 1) & 1) * STAGE_B, pA, pB, tid);
            __syncthreads();
        }
    }

    // ---- epilogue: write fragments with fused op ----
#pragma unroll
    for (int mt = 0; mt < 2; ++mt) {
#pragma unroll
        for (int nt = 0; nt < 8; ++nt) {
            const int rA = row0 + wm * 32 + mt * 16 + (lane >> 2);
            const int cc = col0 + wn * 64 + nt * 8 + (lane & 3) * 2;
#pragma unroll
            for (int half = 0; half < 2; ++half) {
                const int r = rA + half * 8;
                const size_t go = (size_t)r * N + cc;
                float v0 = acc[mt][nt][half * 2 + 0];
                float v1 = acc[mt][nt][half * 2 + 1];
                if (EPI == 0) { v0 += bias[cc]; v1 += bias[cc + 1]; }
                if (EPI == 1) {
                    const float t0 = v0 + bias[cc], t1 = v1 + bias[cc + 1];
                    v0 = 0.5f * t0 * (1.0f + erff(t0 * 0.7071067811865476f));
                    v1 = 0.5f * t1 * (1.0f + erff(t1 * 0.7071067811865476f));
                }
                if (EPI == 2) { v0 += bias[cc]     + res[go];
                                v1 += bias[cc + 1] + res[go + 1]; }
                if (EPI == 3) { v0 *= scale[cc]; v1 *= scale[cc + 1]; }
                if (EPI == 4) { v0 = fmaf(scale[cc],     res[go],     v0);
                                v1 = fmaf(scale[cc + 1], res[go + 1], v1); }
                *(float2*)&Cout[go] = make_float2(v0, v1);
            }
        }
    }
}

// ---------------- launch ----------------
extern "C" void kernel_launch(void* const* d_in, const int* in_sizes, int n_in,
                              void* d_out, int out_size)
{
    (void)in_sizes; (void)n_in; (void)out_size;
    const float* x    = (const float*)d_in[0];
    const float* embW = (const float*)d_in[1];
    const float* embB = (const float*)d_in[2];
    const float* nu   = (const float*)d_in[3];
    const float* th   = (const float*)d_in[4];
    const float* gl   = (const float*)d_in[5];
    const float* Bre  = (const float*)d_in[6];
    const float* Bim  = (const float*)d_in[7];
    const float* Cre  = (const float*)d_in[8];
    const float* Cim  = (const float*)d_in[9];
    const float* Dm   = (const float*)d_in[10];
    const float* Wh   = (const float*)d_in[11];
    const float* bh   = (const float*)d_in[12];
    const float* Wo   = (const float*)d_in[13];
    const float* bo   = (const float*)d_in[14];
    const float* outW = (const float*)d_in[15];
    const float* outB = (const float*)d_in[16];
    float* out = (float*)d_out;

    float *h, *y, *sre, *sim, *z, *eg, *negc;
    cudaGetSymbolAddress((void**)&h,    g_h);
    cudaGetSymbolAddress((void**)&y,    g_y);
    cudaGetSymbolAddress((void**)&sre,  g_sre);
    cudaGetSymbolAddress((void**)&sim,  g_sim);
    cudaGetSymbolAddress((void**)&z,    g_z);
    cudaGetSymbolAddress((void**)&eg,   g_eg);
    cudaGetSymbolAddress((void**)&negc, g_negCim);

    cudaFuncSetAttribute(mma_gemm<0, false>, cudaFuncAttributeMaxDynamicSharedMemorySize, SMEM_BYTES);
    cudaFuncSetAttribute(mma_gemm<1, false>, cudaFuncAttributeMaxDynamicSharedMemorySize, SMEM_BYTES);
    cudaFuncSetAttribute(mma_gemm<2, false>, cudaFuncAttributeMaxDynamicSharedMemorySize, SMEM_BYTES);
    cudaFuncSetAttribute(mma_gemm<3, false>, cudaFuncAttributeMaxDynamicSharedMemorySize, SMEM_BYTES);
    cudaFuncSetAttribute(mma_gemm<4, true >, cudaFuncAttributeMaxDynamicSharedMemorySize, SMEM_BYTES);

    prep_kernel<<<NL, STATE>>>(nu, th, gl);
    neg_kernel<<<(NL * HID * STATE) / 256, 256>>>(Cim);

    const dim3 blk(256);

    // embedding: h = x @ embW^T + embB          (BL x 256, K=64)
    mma_gemm<0, false><<<dim3(HID / 128, BL / 128), blk, SMEM_BYTES>>>(
        x, embW, nullptr, nullptr, h, HID, INDIM, embB, nullptr, nullptr);

    for (int l = 0; l < NL; ++l) {
        // Bu = (h @ B^T) * exp(gamma)[col]      (BL x 256, K=256) x2
        mma_gemm<3, false><<<dim3(STATE / 128, BL / 128), blk, SMEM_BYTES>>>(
            h, Bre + (size_t)l * STATE * HID, nullptr, nullptr, sre,
            STATE, HID, nullptr, eg + l * STATE, nullptr);
        mma_gemm<3, false><<<dim3(STATE / 128, BL / 128), blk, SMEM_BYTES>>>(
            h, Bim + (size_t)l * STATE * HID, nullptr, nullptr, sim,
            STATE, HID, nullptr, eg + l * STATE, nullptr);

        // diagonal complex scan (in place on sre/sim)
        scan_pass1<<<dim3(NC, BATCHN), STATE>>>(l);
        scan_pass2<<<BATCHN, STATE>>>(l, nu, th);
        scan_pass3<<<dim3(NC, BATCHN), STATE>>>(l);

        // y = sre@Cre^T + sim@(-Cim)^T + D[col]*h
        mma_gemm<4, true><<<dim3(HID / 128, BL / 128), blk, SMEM_BYTES>>>(
            sre, Cre + (size_t)l * HID * STATE,
            sim, negc + (size_t)l * HID * STATE, y,
            HID, STATE, nullptr, Dm + l * HID, h);

        // z = gelu(y @ Wh^T + bh)               (BL x 1024, K=256)
        mma_gemm<1, false><<<dim3(MLPD / 128, BL / 128), blk, SMEM_BYTES>>>(
            y, Wh + (size_t)l * MLPD * STATE, nullptr, nullptr, z,
            MLPD, STATE, bh + l * MLPD, nullptr, nullptr);

        // h = z @ Wo^T + bo + y                 (BL x 256, K=1024)
        mma_gemm<2, false><<<dim3(HID / 128, BL / 128), blk, SMEM_BYTES>>>(
            z, Wo + (size_t)l * HID * MLPD, nullptr, nullptr, h,
            HID, MLPD, bo + l * HID, nullptr, y);
    }

    // out = h @ outW^T + outB                   (BL x 128, K=256)
    mma_gemm<0, false><<<dim3(OUTD / 128, BL / 128), blk, SMEM_BYTES>>>(
        h, outW, nullptr, nullptr, out, OUTD, HID, outB, nullptr, nullptr);
}

// round 5
// speedup vs baseline: 2.5184x; 1.0194x over previous
#include <cuda_runtime.h>
#include <math.h>
#include <stdint.h>

// ---------------- problem constants ----------------
#define BATCHN  16
#define LSEQ    2048
#define INDIM   64
#define HID     256
#define STATE   256
#define MLPD    1024
#define OUTD    128
#define NL      4
#define BL      (BATCHN * LSEQ)      // 32768 rows
#define CL      128                  // scan chunk length
#define NC      (LSEQ / CL)          // 16 chunks

// smem tile layout (bytes): rows padded to 80B — conflict-free ldmatrix
// CTA tile: 128(M) x 64(N), K chunk 32
#define LDS_ROW   80
#define T_AH      0
#define T_AL      10240              // 128 rows * 80
#define T_BH      20480
#define T_BL      25600              // 64 rows * 80
#define STAGE_B   30720
#define SMEM_BYTES (2 * STAGE_B)     // 61440 -> 2 CTAs/SM

// ---------------- device scratch (static, no allocations) ----------------
__device__ float g_h  [BL * HID];
__device__ float g_y  [BL * HID];
__device__ float g_sre[BL * STATE];
__device__ float g_sim[BL * STATE];
__device__ float g_z  [BL * MLPD];
__device__ float g_cre[BATCHN * NC * STATE];
__device__ float g_cim[BATCHN * NC * STATE];
__device__ float g_ire[BATCHN * NC * STATE];
__device__ float g_iim[BATCHN * NC * STATE];
__device__ float g_lamre[NL * STATE];
__device__ float g_lamim[NL * STATE];
__device__ float g_eg   [NL * STATE];
__device__ float g_negCim[NL * HID * STATE];

// ---------------- PTX helpers ----------------
__device__ __forceinline__ uint32_t smem_u32(const void* p) {
    uint32_t a;
    asm("{ .reg .u64 t; cvta.to.shared.u64 t, %1; cvt.u32.u64 %0, t; }"
        : "=r"(a) : "l"(p));
    return a;
}
// pack two fp32 -> bf16x2 (x in low half, y in high half)
__device__ __forceinline__ uint32_t cvt2(float x, float y) {
    uint32_t r;
    asm("cvt.rn.bf16x2.f32 %0, %1, %2;" : "=r"(r) : "f"(y), "f"(x));
    return r;
}
__device__ __forceinline__ float lo_of(uint32_t h) { return __uint_as_float(h << 16); }
__device__ __forceinline__ float hi_of(uint32_t h) { return __uint_as_float(h & 0xFFFF0000u); }
__device__ __forceinline__ void sts64(uint32_t a, uint32_t x, uint32_t y) {
    asm volatile("st.shared.v2.b32 [%0], {%1, %2};" :: "r"(a), "r"(x), "r"(y) : "memory");
}
#define LDSM4(r0, r1, r2, r3, addr) \
    asm volatile("ldmatrix.sync.aligned.m8n8.x4.shared.b16 {%0,%1,%2,%3}, [%4];" \
                 : "=r"(r0), "=r"(r1), "=r"(r2), "=r"(r3) : "r"(addr))
#define MMA_BF16(d, a, b) \
    asm volatile("mma.sync.aligned.m16n8k16.row.col.f32.bf16.bf16.f32 " \
                 "{%0,%1,%2,%3},{%4,%5,%6,%7},{%8,%9},{%0,%1,%2,%3};" \
                 : "+f"((d)[0]), "+f"((d)[1]), "+f"((d)[2]), "+f"((d)[3]) \
                 : "r"((a)[0]), "r"((a)[1]), "r"((a)[2]), "r"((a)[3]), \
                   "r"((b)[0]), "r"((b)[1]))

// ---------------- small prep kernels ----------------
__global__ void prep_kernel(const float* __restrict__ nu,
                            const float* __restrict__ th,
                            const float* __restrict__ gl) {
    const int l = blockIdx.x, s = threadIdx.x;
    const int idx = l * STATE + s;
    const float enu = expf(nu[idx]);
    const float eth = expf(th[idx]);
    const float mag = expf(-enu);
    g_lamre[idx] = mag * cosf(eth);
    g_lamim[idx] = mag * sinf(eth);
    g_eg[idx]    = expf(gl[idx]);
}

__global__ void neg_kernel(const float* __restrict__ Cim) {
    const int i = blockIdx.x * 256 + threadIdx.x;
    g_negCim[i] = -Cim[i];
}

// ---------------- chunked complex diagonal scan ----------------
__global__ void scan_pass1(int l) {
    const int s = threadIdx.x, c = blockIdx.x, b = blockIdx.y;
    const float lr = g_lamre[l * STATE + s];
    const float li = g_lamim[l * STATE + s];
    size_t idx = ((size_t)(b * LSEQ + c * CL)) * STATE + s;
    float ar = 0.f, ai = 0.f;
    for (int t = 0; t < CL; ++t, idx += STATE) {
        const float br = g_sre[idx], bi = g_sim[idx];
        const float nr = fmaf(lr, ar, fmaf(-li, ai, br));
        const float ni = fmaf(lr, ai, fmaf( li, ar, bi));
        ar = nr; ai = ni;
        g_sre[idx] = ar; g_sim[idx] = ai;
    }
    const int ci = (b * NC + c) * STATE + s;
    g_cre[ci] = ar; g_cim[ci] = ai;
}

__global__ void scan_pass2(int l, const float* __restrict__ nu,
                           const float* __restrict__ th) {
    const int s = threadIdx.x, b = blockIdx.x;
    const float enu = expf(nu[l * STATE + s]);
    const float eth = expf(th[l * STATE + s]);
    const float r   = expf(-(float)CL * enu);
    const float ang = (float)CL * eth;
    const float Ar = r * cosf(ang), Ai = r * sinf(ang);
    float pr = 0.f, pi = 0.f;
    for (int c = 0; c < NC; ++c) {
        const int ci = (b * NC + c) * STATE + s;
        g_ire[ci] = pr; g_iim[ci] = pi;
        const float cr = g_cre[ci], cii = g_cim[ci];
        const float nr = fmaf(Ar, pr, fmaf(-Ai, pi, cr));
        const float ni = fmaf(Ar, pi, fmaf( Ai, pr, cii));
        pr = nr; pi = ni;
    }
}

__global__ void scan_pass3(int l) {
    const int s = threadIdx.x, c = blockIdx.x, b = blockIdx.y;
    if (c == 0) return;
    const int ci = (b * NC + c) * STATE + s;
    const float fr = g_ire[ci], fi = g_iim[ci];
    if (fr == 0.f && fi == 0.f) return;
    const float lr = g_lamre[l * STATE + s];
    const float li = g_lamim[l * STATE + s];
    float pr = lr, pi = li;
    size_t idx = ((size_t)(b * LSEQ + c * CL)) * STATE + s;
    for (int t = 0; t < CL; ++t, idx += STATE) {
        g_sre[idx] = fmaf(pr, fr, fmaf(-pi, fi, g_sre[idx]));
        g_sim[idx] = fmaf(pr, fi, fmaf( pi, fr, g_sim[idx]));
        const float nr = pr * lr - pi * li;
        const float ni = fmaf(pr, li, pi * lr);
        pr = nr; pi = ni;
    }
}

// ---------------- stage store: fp32 float4 -> hi/lo bf16 smem ----------------
// A: 128 rows x 32 cols (1024 float4 slots), B: 64 rows x 32 cols (512 slots)
__device__ __forceinline__ void store_stage(uint32_t base, const float4* pA,
                                            const float4* pB, int tid)
{
#pragma unroll
    for (int i = 0; i < 4; ++i) {
        const int slot = i * 256 + tid;
        const int r = slot >> 3, c4 = slot & 7;
        const uint32_t off = (uint32_t)(r * LDS_ROW + c4 * 8);
        const float4 f = pA[i];
        const uint32_t h0 = cvt2(f.x, f.y), h1 = cvt2(f.z, f.w);
        const uint32_t l0 = cvt2(f.x - lo_of(h0), f.y - hi_of(h0));
        const uint32_t l1 = cvt2(f.z - lo_of(h1), f.w - hi_of(h1));
        sts64(base + T_AH + off, h0, h1);
        sts64(base + T_AL + off, l0, l1);
    }
#pragma unroll
    for (int i = 0; i < 2; ++i) {
        const int slot = i * 256 + tid;
        const int r = slot >> 3, c4 = slot & 7;
        const uint32_t off = (uint32_t)(r * LDS_ROW + c4 * 8);
        const float4 f = pB[i];
        const uint32_t h0 = cvt2(f.x, f.y), h1 = cvt2(f.z, f.w);
        const uint32_t l0 = cvt2(f.x - lo_of(h0), f.y - hi_of(h0));
        const uint32_t l1 = cvt2(f.z - lo_of(h1), f.w - hi_of(h1));
        sts64(base + T_BH + off, h0, h1);
        sts64(base + T_BL + off, l0, l1);
    }
}

// ---------------- bf16x3 warp-MMA GEMM: C = A(MxK) @ W(NxK)^T + epilogue -----
// CTA tile 128x64; 8 warps in 4(M) x 2(N); warp tile 32x32.
// EPI: 0=+bias 1=gelu(x+bias) 2=+bias+res 3=*scale[col] 4=+scale[col]*res
// DUAL: accumulate a second (A2, W2) product with the same K.
template <int EPI, bool DUAL>
__global__ void __launch_bounds__(256, 2)
mma_gemm(const float* __restrict__ A,  const float* __restrict__ W,
         const float* __restrict__ A2, const float* __restrict__ W2,
         float* __restrict__ Cout, int N, int K,
         const float* __restrict__ bias, const float* __restrict__ scale,
         const float* __restrict__ res)
{
    extern __shared__ char smem[];
    const uint32_t sb = smem_u32(smem);
    const int tid  = threadIdx.x;
    const int lane = tid & 31, wid = tid >> 5;
    const int wm = wid & 3, wn = wid >> 2;          // warp grid 4(M) x 2(N)
    const int row0 = blockIdx.y * 128, col0 = blockIdx.x * 64;

    float acc[2][4][4];
#pragma unroll
    for (int mt = 0; mt < 2; ++mt)
#pragma unroll
        for (int nt = 0; nt < 4; ++nt)
#pragma unroll
            for (int e = 0; e < 4; ++e) acc[mt][nt][e] = 0.f;

    const int KC   = K >> 5;
    const int CTOT = DUAL ? 2 * KC : KC;

    // ldmatrix per-lane offsets (bytes within a hi/lo tile)
    const uint32_t aOff = (uint32_t)((wm * 32 + (lane & 15)) * LDS_ROW + ((lane >> 4) << 4));
    const uint32_t bOff = (uint32_t)((wn * 32 + (((lane >> 4) << 3) | (lane & 7))) * LDS_ROW
                                     + (((lane >> 3) & 1) << 4));

    // prologue: chunk 0
    float4 pA[4], pB[2];
#pragma unroll
    for (int i = 0; i < 4; ++i) {
        const int slot = i * 256 + tid, r = slot >> 3, c4 = slot & 7;
        pA[i] = *(const float4*)(A + (size_t)(row0 + r) * K + c4 * 4);
    }
#pragma unroll
    for (int i = 0; i < 2; ++i) {
        const int slot = i * 256 + tid, r = slot >> 3, c4 = slot & 7;
        pB[i] = *(const float4*)(W + (size_t)(col0 + r) * K + c4 * 4);
    }
    store_stage(sb, pA, pB, tid);
    __syncthreads();

    for (int c = 0; c < CTOT; ++c) {
        if (c + 1 < CTOT) {   // prefetch next chunk to registers
            const int pass = (DUAL && (c + 1) >= KC) ? 1 : 0;
            const int k0 = ((c + 1) - (pass ? KC : 0)) << 5;
            const float* Ap = pass ? A2 : A;
            const float* Wp = pass ? W2 : W;
#pragma unroll
            for (int i = 0; i < 4; ++i) {
                const int slot = i * 256 + tid, r = slot >> 3, c4 = slot & 7;
                pA[i] = *(const float4*)(Ap + (size_t)(row0 + r) * K + k0 + c4 * 4);
            }
#pragma unroll
            for (int i = 0; i < 2; ++i) {
                const int slot = i * 256 + tid, r = slot >> 3, c4 = slot & 7;
                pB[i] = *(const float4*)(Wp + (size_t)(col0 + r) * K + k0 + c4 * 4);
            }
        }
        const uint32_t st = sb + (uint32_t)(c & 1) * STAGE_B;
#pragma unroll
        for (int ks = 0; ks < 2; ++ks) {
            uint32_t ah[2][4], al[2][4], bh[4][2], bl[4][2];
            const uint32_t kb = (uint32_t)(ks * 32);
#pragma unroll
            for (int mt = 0; mt < 2; ++mt) {
                const uint32_t ad = st + aOff + (uint32_t)(mt * 16 * LDS_ROW) + kb;
                LDSM4(ah[mt][0], ah[mt][1], ah[mt][2], ah[mt][3], ad + T_AH);
                LDSM4(al[mt][0], al[mt][1], al[mt][2], al[mt][3], ad + T_AL);
            }
#pragma unroll
            for (int np = 0; np < 2; ++np) {
                const uint32_t bd = st + bOff + (uint32_t)(np * 16 * LDS_ROW) + kb;
                LDSM4(bh[np*2][0], bh[np*2][1], bh[np*2+1][0], bh[np*2+1][1], bd + T_BH);
                LDSM4(bl[np*2][0], bl[np*2][1], bl[np*2+1][0], bl[np*2+1][1], bd + T_BL);
            }
#pragma unroll
            for (int mt = 0; mt < 2; ++mt)
#pragma unroll
                for (int nt = 0; nt < 4; ++nt) {
                    MMA_BF16(acc[mt][nt], ah[mt], bh[nt]);
                    MMA_BF16(acc[mt][nt], al[mt], bh[nt]);
                    MMA_BF16(acc[mt][nt], ah[mt], bl[nt]);
                }
        }
        if (c + 1 < CTOT) {
            __syncthreads();
            store_stage(sb + (uint32_t)((c + 1) & 1) * STAGE_B, pA, pB, tid);
            __syncthreads();
        }
    }

    // ---- epilogue: write fragments with fused op ----
#pragma unroll
    for (int mt = 0; mt < 2; ++mt) {
#pragma unroll
        for (int nt = 0; nt < 4; ++nt) {
            const int rA = row0 + wm * 32 + mt * 16 + (lane >> 2);
            const int cc = col0 + wn * 32 + nt * 8 + (lane & 3) * 2;
#pragma unroll
            for (int half = 0; half < 2; ++half) {
                const int r = rA + half * 8;
                const size_t go = (size_t)r * N + cc;
                float v0 = acc[mt][nt][half * 2 + 0];
                float v1 = acc[mt][nt][half * 2 + 1];
                if (EPI == 0) { v0 += bias[cc]; v1 += bias[cc + 1]; }
                if (EPI == 1) {
                    const float t0 = v0 + bias[cc], t1 = v1 + bias[cc + 1];
                    v0 = 0.5f * t0 * (1.0f + erff(t0 * 0.7071067811865476f));
                    v1 = 0.5f * t1 * (1.0f + erff(t1 * 0.7071067811865476f));
                }
                if (EPI == 2) { v0 += bias[cc]     + res[go];
                                v1 += bias[cc + 1] + res[go + 1]; }
                if (EPI == 3) { v0 *= scale[cc]; v1 *= scale[cc + 1]; }
                if (EPI == 4) { v0 = fmaf(scale[cc],     res[go],     v0);
                                v1 = fmaf(scale[cc + 1], res[go + 1], v1); }
                *(float2*)&Cout[go] = make_float2(v0, v1);
            }
        }
    }
}

// ---------------- launch ----------------
extern "C" void kernel_launch(void* const* d_in, const int* in_sizes, int n_in,
                              void* d_out, int out_size)
{
    (void)in_sizes; (void)n_in; (void)out_size;
    const float* x    = (const float*)d_in[0];
    const float* embW = (const float*)d_in[1];
    const float* embB = (const float*)d_in[2];
    const float* nu   = (const float*)d_in[3];
    const float* th   = (const float*)d_in[4];
    const float* gl   = (const float*)d_in[5];
    const float* Bre  = (const float*)d_in[6];
    const float* Bim  = (const float*)d_in[7];
    const float* Cre  = (const float*)d_in[8];
    const float* Cim  = (const float*)d_in[9];
    const float* Dm   = (const float*)d_in[10];
    const float* Wh   = (const float*)d_in[11];
    const float* bh   = (const float*)d_in[12];
    const float* Wo   = (const float*)d_in[13];
    const float* bo   = (const float*)d_in[14];
    const float* outW = (const float*)d_in[15];
    const float* outB = (const float*)d_in[16];
    float* out = (float*)d_out;

    float *h, *y, *sre, *sim, *z, *eg, *negc;
    cudaGetSymbolAddress((void**)&h,    g_h);
    cudaGetSymbolAddress((void**)&y,    g_y);
    cudaGetSymbolAddress((void**)&sre,  g_sre);
    cudaGetSymbolAddress((void**)&sim,  g_sim);
    cudaGetSymbolAddress((void**)&z,    g_z);
    cudaGetSymbolAddress((void**)&eg,   g_eg);
    cudaGetSymbolAddress((void**)&negc, g_negCim);

    cudaFuncSetAttribute(mma_gemm<0, false>, cudaFuncAttributeMaxDynamicSharedMemorySize, SMEM_BYTES);
    cudaFuncSetAttribute(mma_gemm<1, false>, cudaFuncAttributeMaxDynamicSharedMemorySize, SMEM_BYTES);
    cudaFuncSetAttribute(mma_gemm<2, false>, cudaFuncAttributeMaxDynamicSharedMemorySize, SMEM_BYTES);
    cudaFuncSetAttribute(mma_gemm<3, false>, cudaFuncAttributeMaxDynamicSharedMemorySize, SMEM_BYTES);
    cudaFuncSetAttribute(mma_gemm<4, true >, cudaFuncAttributeMaxDynamicSharedMemorySize, SMEM_BYTES);

    prep_kernel<<<NL, STATE>>>(nu, th, gl);
    neg_kernel<<<(NL * HID * STATE) / 256, 256>>>(Cim);

    const dim3 blk(256);

    // embedding: h = x @ embW^T + embB          (BL x 256, K=64)
    mma_gemm<0, false><<<dim3(HID / 64, BL / 128), blk, SMEM_BYTES>>>(
        x, embW, nullptr, nullptr, h, HID, INDIM, embB, nullptr, nullptr);

    for (int l = 0; l < NL; ++l) {
        // Bu = (h @ B^T) * exp(gamma)[col]      (BL x 256, K=256) x2
        mma_gemm<3, false><<<dim3(STATE / 64, BL / 128), blk, SMEM_BYTES>>>(
            h, Bre + (size_t)l * STATE * HID, nullptr, nullptr, sre,
            STATE, HID, nullptr, eg + l * STATE, nullptr);
        mma_gemm<3, false><<<dim3(STATE / 64, BL / 128), blk, SMEM_BYTES>>>(
            h, Bim + (size_t)l * STATE * HID, nullptr, nullptr, sim,
            STATE, HID, nullptr, eg + l * STATE, nullptr);

        // diagonal complex scan (in place on sre/sim)
        scan_pass1<<<dim3(NC, BATCHN), STATE>>>(l);
        scan_pass2<<<BATCHN, STATE>>>(l, nu, th);
        scan_pass3<<<dim3(NC, BATCHN), STATE>>>(l);

        // y = sre@Cre^T + sim@(-Cim)^T + D[col]*h
        mma_gemm<4, true><<<dim3(HID / 64, BL / 128), blk, SMEM_BYTES>>>(
            sre, Cre + (size_t)l * HID * STATE,
            sim, negc + (size_t)l * HID * STATE, y,
            HID, STATE, nullptr, Dm + l * HID, h);

        // z = gelu(y @ Wh^T + bh)               (BL x 1024, K=256)
        mma_gemm<1, false><<<dim3(MLPD / 64, BL / 128), blk, SMEM_BYTES>>>(
            y, Wh + (size_t)l * MLPD * STATE, nullptr, nullptr, z,
            MLPD, STATE, bh + l * MLPD, nullptr, nullptr);

        // h = z @ Wo^T + bo + y                 (BL x 256, K=1024)
        mma_gemm<2, false><<<dim3(HID / 64, BL / 128), blk, SMEM_BYTES>>>(
            z, Wo + (size_t)l * HID * MLPD, nullptr, nullptr, h,
            HID, MLPD, bo + l * HID, nullptr, y);
    }

    // out = h @ outW^T + outB                   (BL x 128, K=256)
    mma_gemm<0, false><<<dim3(OUTD / 64, BL / 128), blk, SMEM_BYTES>>>(
        h, outW, nullptr, nullptr, out, OUTD, HID, outB, nullptr, nullptr);
}

// round 7
// speedup vs baseline: 2.5338x; 1.0061x over previous
#include <cuda_runtime.h>
#include <math.h>
#include <stdint.h>

// ---------------- problem constants ----------------
#define BATCHN  16
#define LSEQ    2048
#define INDIM   64
#define HID     256
#define STATE   256
#define MLPD    1024
#define OUTD    128
#define NL      4
#define BL      (BATCHN * LSEQ)      // 32768 rows
#define CL      128                  // scan chunk length
#define NC      (LSEQ / CL)          // 16 chunks

// smem tile layout (bytes): rows padded to 80B — conflict-free ldmatrix
// CTA tile: 128(M) x 64(N), K chunk 32; 3-stage pipeline
#define LDS_ROW   80
#define T_AH      0
#define T_AL      10240              // 128 rows * 80
#define T_BH      20480
#define T_BL      25600              // 64 rows * 80
#define STAGE_B   30720
#define SMEM_BYTES (3 * STAGE_B)     // 92160 -> 2 CTAs/SM (184 KB)

// ---------------- device scratch (static, no allocations) ----------------
__device__ float g_h  [BL * HID];
__device__ float g_y  [BL * HID];
__device__ float g_sre[BL * STATE];
__device__ float g_sim[BL * STATE];
__device__ float g_z  [BL * MLPD];
__device__ float g_cre[BATCHN * NC * STATE];
__device__ float g_cim[BATCHN * NC * STATE];
__device__ float g_ire[BATCHN * NC * STATE];
__device__ float g_iim[BATCHN * NC * STATE];
__device__ float g_lamre[NL * STATE];
__device__ float g_lamim[NL * STATE];
__device__ float g_eg   [NL * STATE];
__device__ float g_negCim[NL * HID * STATE];

// ---------------- PTX helpers ----------------
__device__ __forceinline__ uint32_t smem_u32(const void* p) {
    uint32_t a;
    asm("{ .reg .u64 t; cvta.to.shared.u64 t, %1; cvt.u32.u64 %0, t; }"
        : "=r"(a) : "l"(p));
    return a;
}
// pack two fp32 -> bf16x2 (x in low half, y in high half)
__device__ __forceinline__ uint32_t cvt2(float x, float y) {
    uint32_t r;
    asm("cvt.rn.bf16x2.f32 %0, %1, %2;" : "=r"(r) : "f"(y), "f"(x));
    return r;
}
__device__ __forceinline__ float lo_of(uint32_t h) { return __uint_as_float(h << 16); }
__device__ __forceinline__ float hi_of(uint32_t h) { return __uint_as_float(h & 0xFFFF0000u); }
__device__ __forceinline__ void sts64(uint32_t a, uint32_t x, uint32_t y) {
    asm volatile("st.shared.v2.b32 [%0], {%1, %2};" :: "r"(a), "r"(x), "r"(y) : "memory");
}
#define LDSM4(r0, r1, r2, r3, addr) \
    asm volatile("ldmatrix.sync.aligned.m8n8.x4.shared.b16 {%0,%1,%2,%3}, [%4];" \
                 : "=r"(r0), "=r"(r1), "=r"(r2), "=r"(r3) : "r"(addr))
#define MMA_BF16(d, a, b) \
    asm volatile("mma.sync.aligned.m16n8k16.row.col.f32.bf16.bf16.f32 " \
                 "{%0,%1,%2,%3},{%4,%5,%6,%7},{%8,%9},{%0,%1,%2,%3};" \
                 : "+f"((d)[0]), "+f"((d)[1]), "+f"((d)[2]), "+f"((d)[3]) \
                 : "r"((a)[0]), "r"((a)[1]), "r"((a)[2]), "r"((a)[3]), \
                   "r"((b)[0]), "r"((b)[1]))

// ---------------- small prep kernels ----------------
__global__ void prep_kernel(const float* __restrict__ nu,
                            const float* __restrict__ th,
                            const float* __restrict__ gl) {
    const int l = blockIdx.x, s = threadIdx.x;
    const int idx = l * STATE + s;
    const float enu = expf(nu[idx]);
    const float eth = expf(th[idx]);
    const float mag = expf(-enu);
    g_lamre[idx] = mag * cosf(eth);
    g_lamim[idx] = mag * sinf(eth);
    g_eg[idx]    = expf(gl[idx]);
}

__global__ void neg_kernel(const float* __restrict__ Cim) {
    const int i = blockIdx.x * 256 + threadIdx.x;
    g_negCim[i] = -Cim[i];
}

// ---------------- chunked complex diagonal scan ----------------
__global__ void scan_pass1(int l) {
    const int s = threadIdx.x, c = blockIdx.x, b = blockIdx.y;
    const float lr = g_lamre[l * STATE + s];
    const float li = g_lamim[l * STATE + s];
    size_t idx = ((size_t)(b * LSEQ + c * CL)) * STATE + s;
    float ar = 0.f, ai = 0.f;
    for (int t = 0; t < CL; ++t, idx += STATE) {
        const float br = g_sre[idx], bi = g_sim[idx];
        const float nr = fmaf(lr, ar, fmaf(-li, ai, br));
        const float ni = fmaf(lr, ai, fmaf( li, ar, bi));
        ar = nr; ai = ni;
        g_sre[idx] = ar; g_sim[idx] = ai;
    }
    const int ci = (b * NC + c) * STATE + s;
    g_cre[ci] = ar; g_cim[ci] = ai;
}

__global__ void scan_pass2(int l, const float* __restrict__ nu,
                           const float* __restrict__ th) {
    const int s = threadIdx.x, b = blockIdx.x;
    const float enu = expf(nu[l * STATE + s]);
    const float eth = expf(th[l * STATE + s]);
    const float r   = expf(-(float)CL * enu);
    const float ang = (float)CL * eth;
    const float Ar = r * cosf(ang), Ai = r * sinf(ang);
    float pr = 0.f, pi = 0.f;
    for (int c = 0; c < NC; ++c) {
        const int ci = (b * NC + c) * STATE + s;
        g_ire[ci] = pr; g_iim[ci] = pi;
        const float cr = g_cre[ci], cii = g_cim[ci];
        const float nr = fmaf(Ar, pr, fmaf(-Ai, pi, cr));
        const float ni = fmaf(Ar, pi, fmaf( Ai, pr, cii));
        pr = nr; pi = ni;
    }
}

__global__ void scan_pass3(int l) {
    const int s = threadIdx.x, c = blockIdx.x, b = blockIdx.y;
    if (c == 0) return;
    const int ci = (b * NC + c) * STATE + s;
    const float fr = g_ire[ci], fi = g_iim[ci];
    if (fr == 0.f && fi == 0.f) return;
    const float lr = g_lamre[l * STATE + s];
    const float li = g_lamim[l * STATE + s];
    float pr = lr, pi = li;
    size_t idx = ((size_t)(b * LSEQ + c * CL)) * STATE + s;
    for (int t = 0; t < CL; ++t, idx += STATE) {
        g_sre[idx] = fmaf(pr, fr, fmaf(-pi, fi, g_sre[idx]));
        g_sim[idx] = fmaf(pr, fi, fmaf( pi, fr, g_sim[idx]));
        const float nr = pr * lr - pi * li;
        const float ni = fmaf(pr, li, pi * lr);
        pr = nr; pi = ni;
    }
}

// ---------------- stage store: fp32 float4 -> hi/lo bf16 smem ----------------
// A: 128 rows x 32 cols (1024 float4 slots), B: 64 rows x 32 cols (512 slots)
__device__ __forceinline__ void store_stage(uint32_t base, const float4* pA,
                                            const float4* pB, int tid)
{
#pragma unroll
    for (int i = 0; i < 4; ++i) {
        const int slot = i * 256 + tid;
        const int r = slot >> 3, c4 = slot & 7;
        const uint32_t off = (uint32_t)(r * LDS_ROW + c4 * 8);
        const float4 f = pA[i];
        const uint32_t h0 = cvt2(f.x, f.y), h1 = cvt2(f.z, f.w);
        const uint32_t l0 = cvt2(f.x - lo_of(h0), f.y - hi_of(h0));
        const uint32_t l1 = cvt2(f.z - lo_of(h1), f.w - hi_of(h1));
        sts64(base + T_AH + off, h0, h1);
        sts64(base + T_AL + off, l0, l1);
    }
#pragma unroll
    for (int i = 0; i < 2; ++i) {
        const int slot = i * 256 + tid;
        const int r = slot >> 3, c4 = slot & 7;
        const uint32_t off = (uint32_t)(r * LDS_ROW + c4 * 8);
        const float4 f = pB[i];
        const uint32_t h0 = cvt2(f.x, f.y), h1 = cvt2(f.z, f.w);
        const uint32_t l0 = cvt2(f.x - lo_of(h0), f.y - hi_of(h0));
        const uint32_t l1 = cvt2(f.z - lo_of(h1), f.w - hi_of(h1));
        sts64(base + T_BH + off, h0, h1);
        sts64(base + T_BL + off, l0, l1);
    }
}

// ---------------- bf16x3 warp-MMA GEMM: C = A(MxK) @ W(NxK)^T + epilogue -----
// CTA tile 128x64; 8 warps in 4(M) x 2(N); warp tile 32x32.
// 3-stage smem pipeline, ONE __syncthreads per k-chunk; STS hidden under MMA.
// EPI: 0=+bias 1=gelu(x+bias) 2=+bias+res 3=*scale[col] 4=+scale[col]*res
// DUAL: accumulate a second (A2, W2) product with the same K.
template <int EPI, bool DUAL>
__global__ void __launch_bounds__(256, 2)
mma_gemm(const float* __restrict__ A,  const float* __restrict__ W,
         const float* __restrict__ A2, const float* __restrict__ W2,
         float* __restrict__ Cout, int N, int K,
         const float* __restrict__ bias, const float* __restrict__ scale,
         const float* __restrict__ res)
{
    extern __shared__ char smem[];
    const uint32_t sb = smem_u32(smem);
    const int tid  = threadIdx.x;
    const int lane = tid & 31, wid = tid >> 5;
    const int wm = wid & 3, wn = wid >> 2;          // warp grid 4(M) x 2(N)
    const int row0 = blockIdx.y * 128, col0 = blockIdx.x * 64;

    float acc[2][4][4];
#pragma unroll
    for (int mt = 0; mt < 2; ++mt)
#pragma unroll
        for (int nt = 0; nt < 4; ++nt)
#pragma unroll
            for (int e = 0; e < 4; ++e) acc[mt][nt][e] = 0.f;

    const int KC   = K >> 5;
    const int CTOT = DUAL ? 2 * KC : KC;

    // ldmatrix per-lane offsets (bytes within a hi/lo tile)
    const uint32_t aOff = (uint32_t)((wm * 32 + (lane & 15)) * LDS_ROW + ((lane >> 4) << 4));
    const uint32_t bOff = (uint32_t)((wn * 32 + (((lane >> 4) << 3) | (lane & 7))) * LDS_ROW
                                     + (((lane >> 3) & 1) << 4));

    float4 pA[4], pB[2];

    // register-load of chunk c
    auto ldchunk = [&](int c) {
        const int pass = (DUAL && c >= KC) ? 1 : 0;
        const int k0 = (c - (pass ? KC : 0)) << 5;
        const float* Ap = pass ? A2 : A;
        const float* Wp = pass ? W2 : W;
#pragma unroll
        for (int i = 0; i < 4; ++i) {
            const int slot = i * 256 + tid, r = slot >> 3, c4 = slot & 7;
            pA[i] = *(const float4*)(Ap + (size_t)(row0 + r) * K + k0 + c4 * 4);
        }
#pragma unroll
        for (int i = 0; i < 2; ++i) {
            const int slot = i * 256 + tid, r = slot >> 3, c4 = slot & 7;
            pB[i] = *(const float4*)(Wp + (size_t)(col0 + r) * K + k0 + c4 * 4);
        }
    };

    // prologue: chunk 0 staged, chunk 1 in registers
    ldchunk(0);
    store_stage(sb, pA, pB, tid);
    if (CTOT > 1) ldchunk(1);
    __syncthreads();

    int bufC = 0, bufS = 1;                         // compute buf, store buf
    for (int c = 0; c < CTOT; ++c) {
        // stage chunk c+1 into its buffer (safe: last read was iter c-2,
        // fenced by that iteration's barrier), then prefetch chunk c+2
        if (c + 1 < CTOT)
            store_stage(sb + (uint32_t)bufS * STAGE_B, pA, pB, tid);
        if (c + 2 < CTOT) ldchunk(c + 2);

        const uint32_t st = sb + (uint32_t)bufC * STAGE_B;
#pragma unroll
        for (int ks = 0; ks < 2; ++ks) {
            uint32_t ah[2][4], al[2][4], bh[4][2], bl[4][2];
            const uint32_t kb = (uint32_t)(ks * 32);
#pragma unroll
            for (int mt = 0; mt < 2; ++mt) {
                const uint32_t ad = st + aOff + (uint32_t)(mt * 16 * LDS_ROW) + kb;
                LDSM4(ah[mt][0], ah[mt][1], ah[mt][2], ah[mt][3], ad + T_AH);
                LDSM4(al[mt][0], al[mt][1], al[mt][2], al[mt][3], ad + T_AL);
            }
#pragma unroll
            for (int np = 0; np < 2; ++np) {
                const uint32_t bd = st + bOff + (uint32_t)(np * 16 * LDS_ROW) + kb;
                LDSM4(bh[np*2][0], bh[np*2][1], bh[np*2+1][0], bh[np*2+1][1], bd + T_BH);
                LDSM4(bl[np*2][0], bl[np*2][1], bl[np*2+1][0], bl[np*2+1][1], bd + T_BL);
            }
#pragma unroll
            for (int mt = 0; mt < 2; ++mt)
#pragma unroll
                for (int nt = 0; nt < 4; ++nt) {
                    MMA_BF16(acc[mt][nt], ah[mt], bh[nt]);
                    MMA_BF16(acc[mt][nt], al[mt], bh[nt]);
                    MMA_BF16(acc[mt][nt], ah[mt], bl[nt]);
                }
        }
        __syncthreads();
        bufC = (bufC == 2) ? 0 : bufC + 1;
        bufS = (bufS == 2) ? 0 : bufS + 1;
    }

    // ---- epilogue: write fragments with fused op ----
#pragma unroll
    for (int mt = 0; mt < 2; ++mt) {
#pragma unroll
        for (int nt = 0; nt < 4; ++nt) {
            const int rA = row0 + wm * 32 + mt * 16 + (lane >> 2);
            const int cc = col0 + wn * 32 + nt * 8 + (lane & 3) * 2;
#pragma unroll
            for (int half = 0; half < 2; ++half) {
                const int r = rA + half * 8;
                const size_t go = (size_t)r * N + cc;
                float v0 = acc[mt][nt][half * 2 + 0];
                float v1 = acc[mt][nt][half * 2 + 1];
                if (EPI == 0) { v0 += bias[cc]; v1 += bias[cc + 1]; }
                if (EPI == 1) {
                    const float t0 = v0 + bias[cc], t1 = v1 + bias[cc + 1];
                    v0 = 0.5f * t0 * (1.0f + erff(t0 * 0.7071067811865476f));
                    v1 = 0.5f * t1 * (1.0f + erff(t1 * 0.7071067811865476f));
                }
                if (EPI == 2) { v0 += bias[cc]     + res[go];
                                v1 += bias[cc + 1] + res[go + 1]; }
                if (EPI == 3) { v0 *= scale[cc]; v1 *= scale[cc + 1]; }
                if (EPI == 4) { v0 = fmaf(scale[cc],     res[go],     v0);
                                v1 = fmaf(scale[cc + 1], res[go + 1], v1); }
                *(float2*)&Cout[go] = make_float2(v0, v1);
            }
        }
    }
}

// ---------------- launch ----------------
extern "C" void kernel_launch(void* const* d_in, const int* in_sizes, int n_in,
                              void* d_out, int out_size)
{
    (void)in_sizes; (void)n_in; (void)out_size;
    const float* x    = (const float*)d_in[0];
    const float* embW = (const float*)d_in[1];
    const float* embB = (const float*)d_in[2];
    const float* nu   = (const float*)d_in[3];
    const float* th   = (const float*)d_in[4];
    const float* gl   = (const float*)d_in[5];
    const float* Bre  = (const float*)d_in[6];
    const float* Bim  = (const float*)d_in[7];
    const float* Cre  = (const float*)d_in[8];
    const float* Cim  = (const float*)d_in[9];
    const float* Dm   = (const float*)d_in[10];
    const float* Wh   = (const float*)d_in[11];
    const float* bh   = (const float*)d_in[12];
    const float* Wo   = (const float*)d_in[13];
    const float* bo   = (const float*)d_in[14];
    const float* outW = (const float*)d_in[15];
    const float* outB = (const float*)d_in[16];
    float* out = (float*)d_out;

    float *h, *y, *sre, *sim, *z, *eg, *negc;
    cudaGetSymbolAddress((void**)&h,    g_h);
    cudaGetSymbolAddress((void**)&y,    g_y);
    cudaGetSymbolAddress((void**)&sre,  g_sre);
    cudaGetSymbolAddress((void**)&sim,  g_sim);
    cudaGetSymbolAddress((void**)&z,    g_z);
    cudaGetSymbolAddress((void**)&eg,   g_eg);
    cudaGetSymbolAddress((void**)&negc, g_negCim);

    cudaFuncSetAttribute(mma_gemm<0, false>, cudaFuncAttributeMaxDynamicSharedMemorySize, SMEM_BYTES);
    cudaFuncSetAttribute(mma_gemm<1, false>, cudaFuncAttributeMaxDynamicSharedMemorySize, SMEM_BYTES);
    cudaFuncSetAttribute(mma_gemm<2, false>, cudaFuncAttributeMaxDynamicSharedMemorySize, SMEM_BYTES);
    cudaFuncSetAttribute(mma_gemm<3, false>, cudaFuncAttributeMaxDynamicSharedMemorySize, SMEM_BYTES);
    cudaFuncSetAttribute(mma_gemm<4, true >, cudaFuncAttributeMaxDynamicSharedMemorySize, SMEM_BYTES);

    prep_kernel<<<NL, STATE>>>(nu, th, gl);
    neg_kernel<<<(NL * HID * STATE) / 256, 256>>>(Cim);

    const dim3 blk(256);

    // embedding: h = x @ embW^T + embB          (BL x 256, K=64)
    mma_gemm<0, false><<<dim3(HID / 64, BL / 128), blk, SMEM_BYTES>>>(
        x, embW, nullptr, nullptr, h, HID, INDIM, embB, nullptr, nullptr);

    for (int l = 0; l < NL; ++l) {
        // Bu = (h @ B^T) * exp(gamma)[col]      (BL x 256, K=256) x2
        mma_gemm<3, false><<<dim3(STATE / 64, BL / 128), blk, SMEM_BYTES>>>(
            h, Bre + (size_t)l * STATE * HID, nullptr, nullptr, sre,
            STATE, HID, nullptr, eg + l * STATE, nullptr);
        mma_gemm<3, false><<<dim3(STATE / 64, BL / 128), blk, SMEM_BYTES>>>(
            h, Bim + (size_t)l * STATE * HID, nullptr, nullptr, sim,
            STATE, HID, nullptr, eg + l * STATE, nullptr);

        // diagonal complex scan (in place on sre/sim)
        scan_pass1<<<dim3(NC, BATCHN), STATE>>>(l);
        scan_pass2<<<BATCHN, STATE>>>(l, nu, th);
        scan_pass3<<<dim3(NC, BATCHN), STATE>>>(l);

        // y = sre@Cre^T + sim@(-Cim)^T + D[col]*h
        mma_gemm<4, true><<<dim3(HID / 64, BL / 128), blk, SMEM_BYTES>>>(
            sre, Cre + (size_t)l * HID * STATE,
            sim, negc + (size_t)l * HID * STATE, y,
            HID, STATE, nullptr, Dm + l * HID, h);

        // z = gelu(y @ Wh^T + bh)               (BL x 1024, K=256)
        mma_gemm<1, false><<<dim3(MLPD / 64, BL / 128), blk, SMEM_BYTES>>>(
            y, Wh + (size_t)l * MLPD * STATE, nullptr, nullptr, z,
            MLPD, STATE, bh + l * MLPD, nullptr, nullptr);

        // h = z @ Wo^T + bo + y                 (BL x 256, K=1024)
        mma_gemm<2, false><<<dim3(HID / 64, BL / 128), blk, SMEM_BYTES>>>(
            z, Wo + (size_t)l * HID * MLPD, nullptr, nullptr, h,
            HID, MLPD, bo + l * HID, nullptr, y);
    }

    // out = h @ outW^T + outB                   (BL x 128, K=256)
    mma_gemm<0, false><<<dim3(OUTD / 64, BL / 128), blk, SMEM_BYTES>>>(
        h, outW, nullptr, nullptr, out, OUTD, HID, outB, nullptr, nullptr);
}